// round 6
// baseline (speedup 1.0000x reference)
#include <cuda_runtime.h>
#include <cuda_bf16.h>

// loss[s] = -(1/496)*[ sum_i x_i*(31-i) - sum_{i<j} ln(e_i+e_j) + 0.0005*sum_i x_i^2*(31-2i) ]
// via log_sigmoid(x_i - x_j) == x_i - ln(e^{x_i} + e^{x_j}).
//
// sum_{pairs} ln = ln(prod): per lane, two renorm-free 8-term fp32 products,
// ONE lg2 at the end. Fully SCALAR (no f32x2 packing -> no register-pair MOV
// overhead). 4 segments per warp as 4 independent chains; interleaved float2
// rings so one LDS.64 feeds two chains.

static constexpr float INV_PAIRS = 1.0f / 496.0f;
static constexpr float LN2  = 0.69314718055994530942f;
static constexpr float L2E  = 1.44269504088896340736f;
static constexpr int   WPB  = 4;                 // warps per block (128 thr)
static constexpr int   SEG_PER_BLOCK = WPB * 4;  // 16

typedef unsigned int u32;

__device__ __forceinline__ float ex2(float x) {
    float r; asm("ex2.approx.f32 %0,%1;" : "=f"(r) : "f"(x)); return r;
}
__device__ __forceinline__ float lg2(float x) {
    float r; asm("lg2.approx.f32 %0,%1;" : "=f"(r) : "f"(x)); return r;
}
// log2 of (p*q) where p,q are renorm-free partial products:
// (Ep + Eq - 254) + lg2(mp*mq), with mp*mq in [1,4).
__device__ __forceinline__ float log2prod(float p, float q) {
    u32 bp = __float_as_uint(p), bq = __float_as_uint(q);
    int  e  = (int)(bp >> 23) + (int)(bq >> 23) - 254;
    float mp = __uint_as_float((bp & 0x007FFFFFu) | 0x3F800000u);
    float mq = __uint_as_float((bq & 0x007FFFFFu) | 0x3F800000u);
    return (float)e + lg2(mp * mq);
}

__global__ __launch_bounds__(WPB * 32)
void rmloss_kernel(const float* __restrict__ logits,
                   float4* __restrict__ out,
                   int n_seg)
{
    __shared__ float2 r01[WPB][64];   // interleaved (seg0, seg1), duplicated ring
    __shared__ float2 r23[WPB][64];   // interleaved (seg2, seg3), duplicated ring

    const int w    = threadIdx.x >> 5;
    const int lane = threadIdx.x & 31;
    const int gw   = blockIdx.x * WPB + w;
    const int s0   = gw * 4;                        // 4 segments per warp
    if (s0 >= n_seg) return;

    const float* base = logits + s0 * 32 + lane;
    const float x0 = base[0],  x1 = base[32];
    const float x2 = base[64], x3 = base[96];

    // e = exp(x) = exp2(x * log2e)
    const float e0 = ex2(x0 * L2E);
    const float e1 = ex2(x1 * L2E);
    const float e2 = ex2(x2 * L2E);
    const float e3 = ex2(x3 * L2E);

    // Duplicated interleaved rings -> pair reads are LDS.64 [base + imm].
    const float2 v01 = make_float2(e0, e1);
    const float2 v23 = make_float2(e2, e3);
    r01[w][lane] = v01;  r01[w][lane + 32] = v01;
    r23[w][lane] = v23;  r23[w][lane + 32] = v23;
    __syncwarp();

    // Products of pair terms (e_l + e_{l+o}). Offsets 1..15 hit each unordered
    // pair exactly once; offset 16 only for lanes 0..15 (FSEL to 1.0 on upper
    // half). Two 8-term accumulators per segment: renorm-free (<= 2^+-72).
    float2 a = r01[w][lane + 1], b = r23[w][lane + 1];
    float pa0 = e0 + a.x, pa1 = e1 + a.y, pa2 = e2 + b.x, pa3 = e3 + b.y;
    #pragma unroll
    for (int o = 2; o <= 8; ++o) {
        a = r01[w][lane + o];  b = r23[w][lane + o];
        pa0 *= e0 + a.x;  pa1 *= e1 + a.y;
        pa2 *= e2 + b.x;  pa3 *= e3 + b.y;
    }
    a = r01[w][lane + 9];  b = r23[w][lane + 9];
    float pb0 = e0 + a.x, pb1 = e1 + a.y, pb2 = e2 + b.x, pb3 = e3 + b.y;
    #pragma unroll
    for (int o = 10; o <= 15; ++o) {
        a = r01[w][lane + o];  b = r23[w][lane + o];
        pb0 *= e0 + a.x;  pb1 *= e1 + a.y;
        pb2 *= e2 + b.x;  pb3 *= e3 + b.y;
    }
    {   // offset 16: lanes >= 16 contribute a factor of 1.0 (FSEL, no branch)
        a = r01[w][lane + 16];  b = r23[w][lane + 16];
        const bool m = (lane < 16);
        pb0 *= m ? (e0 + a.x) : 1.0f;
        pb1 *= m ? (e1 + a.y) : 1.0f;
        pb2 *= m ? (e2 + b.x) : 1.0f;
        pb3 *= m ? (e3 + b.y) : 1.0f;
    }

    // One lg2 per segment: log2(pa*pb) via exponent extraction.
    const float slg0 = log2prod(pa0, pb0);
    const float slg1 = log2prod(pa1, pb1);
    const float slg2 = log2prod(pa2, pb2);
    const float slg3 = log2prod(pa3, pb3);

    // Per-lane coefficients with all scales folded in:
    //   v = x*(-(31-l)/496) + x^2*(-0.0005*(31-2l)/496) + slg*(ln2/496)
    const float CL  = (float)(31 - lane)     * (-INV_PAIRS);
    const float CQ  = (float)(31 - 2 * lane) * (-0.0005f * INV_PAIRS);
    const float CLN = LN2 * INV_PAIRS;

    float t0 = fmaf(x0, CL, slg0 * CLN);  t0 = fmaf(x0 * x0, CQ, t0);
    float t1 = fmaf(x1, CL, slg1 * CLN);  t1 = fmaf(x1 * x1, CQ, t1);
    float t2 = fmaf(x2, CL, slg2 * CLN);  t2 = fmaf(x2 * x2, CQ, t2);
    float t3 = fmaf(x3, CL, slg3 * CLN);  t3 = fmaf(x3 * x3, CQ, t3);

    // Butterfly reduction: 4 independent scalar chains.
    #pragma unroll
    for (int m = 16; m >= 1; m >>= 1) {
        t0 += __shfl_xor_sync(0xFFFFFFFFu, t0, m);
        t1 += __shfl_xor_sync(0xFFFFFFFFu, t1, m);
        t2 += __shfl_xor_sync(0xFFFFFFFFu, t2, m);
        t3 += __shfl_xor_sync(0xFFFFFFFFu, t3, m);
    }

    if (lane == 0)
        out[gw] = make_float4(t0, t1, t2, t3);   // STG.128, coalesced per-warp
}

extern "C" void kernel_launch(void* const* d_in, const int* in_sizes, int n_in,
                              void* d_out, int out_size)
{
    const float* logits = (const float*)d_in[0];
    float4* out = (float4*)d_out;
    const int n_seg = out_size;                  // 32768

    const int threads = WPB * 32;                // 128
    const int blocks = (n_seg + SEG_PER_BLOCK - 1) / SEG_PER_BLOCK;   // 2048
    rmloss_kernel<<<blocks, threads>>>(logits, out, n_seg);
}